// round 8
// baseline (speedup 1.0000x reference)
#include <cuda_runtime.h>
#include <cuda_fp16.h>
#include <cuda_bf16.h>

namespace {
constexpr int kNUser = 50000;
constexpr int kN     = 80000;      // total nodes
constexpr int kE     = 1000000;    // 2 * NNZ symmetric edges
constexpr int kD     = 64;
constexpr int kChunk = 1024;
constexpr int kNChunk = (kN + kChunk - 1) / kChunk;   // 79
}

// ---------------- device scratch (static, no allocation) ----------------
__device__ float g_A[kE * 4];         // routing logits, CSR-slot order
__device__ float g_normA[kE * 4];     // softmax(A), CSR-slot order
__device__ float g_buf0[kN * kD];     // initial ego (layer-0 input; never overwritten)
__device__ float g_buf1[kN * kD];     // layer-0 output = layer-1 input
__device__ __half2 g_egoS[kN * 32];   // layer ego prescaled by current dinv (fp16, 128B/node)
__device__ uint4 g_TnV[kN * 8];       // tanh(normalized tail chunks), fp16, 128B/node
__device__ float g_dinvA[kN * 4];     // 1/sqrt(degree-weight), ping
__device__ float g_dinvB[kN * 4];     // pong
__device__ int   g_ptr[kN + 1];       // CSR row pointers (by head)
__device__ int   g_cnt[kN];           // histogram / fill counters
__device__ int   g_csr_t[kE];         // tail node per CSR slot
__device__ int   g_bsum[kNChunk];     // per-chunk sums for multi-block scan

__device__ __forceinline__ unsigned pack_h2(float a, float b) {
    __half2 h = __floats2half2_rn(a, b);
    return *reinterpret_cast<unsigned*>(&h);
}

// ---------------- init ----------------
__global__ void k_init_ego(const float* __restrict__ user, const float* __restrict__ item) {
    int i = blockIdx.x * blockDim.x + threadIdx.x;
    if (i >= kN * kD) return;
    g_buf0[i] = (i < kNUser * kD) ? user[i] : item[i - kNUser * kD];
}

__global__ void k_zero_cnt() {
    int i = blockIdx.x * blockDim.x + threadIdx.x;
    if (i < kN) g_cnt[i] = 0;
}

// A=1, normA=0.25 everywhere (slot-independent) -- coalesced
__global__ void k_init_A() {
    int i = blockIdx.x * blockDim.x + threadIdx.x;
    if (i >= kE) return;
    reinterpret_cast<float4*>(g_A)[i]     = make_float4(1.f, 1.f, 1.f, 1.f);
    reinterpret_cast<float4*>(g_normA)[i] = make_float4(.25f, .25f, .25f, .25f);
}

// ---------------- CSR build ----------------
__global__ void k_count(const int* __restrict__ h) {
    int e = blockIdx.x * blockDim.x + threadIdx.x;
    if (e >= kE) return;
    atomicAdd(&g_cnt[h[e]], 1);
}

__global__ void k_chunk_reduce() {            // kNChunk blocks x 256
    __shared__ int wsum[8];
    const int lane = threadIdx.x & 31, wrp = threadIdx.x >> 5;
    int base = blockIdx.x * kChunk + (int)threadIdx.x * 4;
    int s = 0;
    #pragma unroll
    for (int k = 0; k < 4; k++) { int i = base + k; if (i < kN) s += g_cnt[i]; }
    #pragma unroll
    for (int o = 16; o >= 1; o >>= 1) s += __shfl_xor_sync(0xffffffffu, s, o);
    if (lane == 0) wsum[wrp] = s;
    __syncthreads();
    if (threadIdx.x == 0) {
        int t = 0;
        #pragma unroll
        for (int k = 0; k < 8; k++) t += wsum[k];
        g_bsum[blockIdx.x] = t;
    }
}

__global__ void k_bsum_scan() {               // 1 block x 32
    const int lane = threadIdx.x;
    int carry = 0;
    for (int base = 0; base < kNChunk; base += 32) {
        int i = base + lane;
        int v = (i < kNChunk) ? g_bsum[i] : 0;
        int x = v;
        #pragma unroll
        for (int o = 1; o < 32; o <<= 1) {
            int y = __shfl_up_sync(0xffffffffu, x, o);
            if (lane >= o) x += y;
        }
        if (i < kNChunk) g_bsum[i] = carry + x - v;     // exclusive
        carry += __shfl_sync(0xffffffffu, x, 31);
    }
    if (lane == 0) g_ptr[kN] = carry;
}

__global__ void k_chunk_scan() {              // kNChunk blocks x 256
    __shared__ int wsum[8];
    const int lane = threadIdx.x & 31, wrp = threadIdx.x >> 5;
    int base = blockIdx.x * kChunk + (int)threadIdx.x * 4;
    int v0 = 0, v1 = 0, v2 = 0, v3 = 0;
    if (base + 3 < kN) {
        int4 v = *reinterpret_cast<const int4*>(&g_cnt[base]);
        v0 = v.x; v1 = v.y; v2 = v.z; v3 = v.w;
    } else {
        if (base + 0 < kN) v0 = g_cnt[base + 0];
        if (base + 1 < kN) v1 = g_cnt[base + 1];
        if (base + 2 < kN) v2 = g_cnt[base + 2];
        if (base + 3 < kN) v3 = g_cnt[base + 3];
    }
    int tot = v0 + v1 + v2 + v3;
    int x = tot;
    #pragma unroll
    for (int o = 1; o < 32; o <<= 1) {
        int y = __shfl_up_sync(0xffffffffu, x, o);
        if (lane >= o) x += y;
    }
    if (lane == 31) wsum[wrp] = x;
    __syncthreads();
    if (wrp == 0 && lane < 8) {
        int s = wsum[lane], xs = s;
        #pragma unroll
        for (int o = 1; o < 8; o <<= 1) {
            int y = __shfl_up_sync(0xffu, xs, o);
            if (lane >= o) xs += y;
        }
        wsum[lane] = xs - s;
    }
    __syncthreads();
    int ex = g_bsum[blockIdx.x] + wsum[wrp] + (x - tot);
    if (base + 0 < kN) { g_ptr[base + 0] = ex;                g_cnt[base + 0] = 0; }
    if (base + 1 < kN) { g_ptr[base + 1] = ex + v0;           g_cnt[base + 1] = 0; }
    if (base + 2 < kN) { g_ptr[base + 2] = ex + v0 + v1;      g_cnt[base + 2] = 0; }
    if (base + 3 < kN) { g_ptr[base + 3] = ex + v0 + v1 + v2; g_cnt[base + 3] = 0; }
}

// fill CSR (tail ids only; A/normA initialized coalesced elsewhere)
__global__ void k_fill(const int* __restrict__ h, const int* __restrict__ t) {
    int e = blockIdx.x * blockDim.x + threadIdx.x;
    if (e >= kE) return;
    int hn   = h[e];
    int slot = g_ptr[hn] + atomicAdd(&g_cnt[hn], 1);
    g_csr_t[slot] = t[e];
}

// initial dinv: normA = 0.25 everywhere -> dval = 0.25 * deg
__global__ void k_dinv0() {
    int n = blockIdx.x * blockDim.x + threadIdx.x;
    if (n >= kN) return;
    float dval = 0.25f * (float)(g_ptr[n + 1] - g_ptr[n]);
    float di = rsqrtf(fmaxf(dval, 1e-8f));
    reinterpret_cast<float4*>(g_dinvA)[n] = make_float4(di, di, di, di);
}

// ---------------- per-layer: tanh(normalized tail chunks)->fp16 + egoS(fp16) = ego*dinvA ----------------
__global__ void k_tail(int sel) {
    const float* ego = sel ? g_buf1 : g_buf0;
    int i = blockIdx.x * blockDim.x + threadIdx.x;   // (node, factor)
    if (i >= kN * 4) return;
    const float4* src = reinterpret_cast<const float4*>(ego) + i * 4;
    float4 v0 = src[0], v1 = src[1], v2 = src[2], v3 = src[3];
    float ss = v0.x*v0.x + v0.y*v0.y + v0.z*v0.z + v0.w*v0.w
             + v1.x*v1.x + v1.y*v1.y + v1.z*v1.z + v1.w*v1.w
             + v2.x*v2.x + v2.y*v2.y + v2.z*v2.z + v2.w*v2.w
             + v3.x*v3.x + v3.y*v3.y + v3.z*v3.z + v3.w*v3.w;
    float inv = 1.0f / fmaxf(sqrtf(ss), 1e-12f);
    uint4 u0, u1;
    u0.x = pack_h2(tanhf(v0.x*inv), tanhf(v0.y*inv));
    u0.y = pack_h2(tanhf(v0.z*inv), tanhf(v0.w*inv));
    u0.z = pack_h2(tanhf(v1.x*inv), tanhf(v1.y*inv));
    u0.w = pack_h2(tanhf(v1.z*inv), tanhf(v1.w*inv));
    u1.x = pack_h2(tanhf(v2.x*inv), tanhf(v2.y*inv));
    u1.y = pack_h2(tanhf(v2.z*inv), tanhf(v2.w*inv));
    u1.z = pack_h2(tanhf(v3.x*inv), tanhf(v3.y*inv));
    u1.w = pack_h2(tanhf(v3.z*inv), tanhf(v3.w*inv));
    g_TnV[i * 2]     = u0;
    g_TnV[i * 2 + 1] = u1;
    float di = g_dinvA[i];
    uint4 s0, s1;
    s0.x = pack_h2(v0.x*di, v0.y*di);
    s0.y = pack_h2(v0.z*di, v0.w*di);
    s0.z = pack_h2(v1.x*di, v1.y*di);
    s0.w = pack_h2(v1.z*di, v1.w*di);
    s1.x = pack_h2(v2.x*di, v2.y*di);
    s1.y = pack_h2(v2.z*di, v2.w*di);
    s1.z = pack_h2(v3.x*di, v3.y*di);
    s1.w = pack_h2(v3.z*di, v3.w*di);
    reinterpret_cast<uint4*>(g_egoS)[i * 2]     = s0;
    reinterpret_cast<uint4*>(g_egoS)[i * 2 + 1] = s1;
}

// ---------------- between iterations: egoS(fp16) = ego * dinvB (coalesced) ----------------
__global__ void k_rescale(int sel) {
    const float* ego = sel ? g_buf1 : g_buf0;
    int i = blockIdx.x * blockDim.x + threadIdx.x;   // (node, factor)
    if (i >= kN * 4) return;
    const float4* src = reinterpret_cast<const float4*>(ego) + i * 4;
    float di = g_dinvB[i];
    float4 v0 = src[0], v1 = src[1], v2 = src[2], v3 = src[3];
    uint4 s0, s1;
    s0.x = pack_h2(v0.x*di, v0.y*di);
    s0.y = pack_h2(v0.z*di, v0.w*di);
    s0.z = pack_h2(v1.x*di, v1.y*di);
    s0.w = pack_h2(v1.z*di, v1.w*di);
    s1.x = pack_h2(v2.x*di, v2.y*di);
    s1.y = pack_h2(v2.z*di, v2.w*di);
    s1.z = pack_h2(v3.x*di, v3.y*di);
    s1.w = pack_h2(v3.z*di, v3.w*di);
    reinterpret_cast<uint4*>(g_egoS)[i * 2]     = s0;
    reinterpret_cast<uint4*>(g_egoS)[i * 2 + 1] = s1;
}

// ---------------- fused iteration ----------------
// one warp per node. MP: lane owns dims [2l,2l+1] (one __half2), factor f = lane>>3,
// smem-staged edge weights; each egoS row = 128B -> 1 L1tex line per edge.
// Routing: half-warp per edge; 16 lanes read a 128B fp16 Tn row -> 1 line per edge.
// mode: 0 = routing, fe NOT written; 1 = routing + fe write; 2 = final output.
__global__ void __launch_bounds__(256) k_fused(
        int sel_in, int dsel, int mode, float* __restrict__ out)
{
    __shared__ int    sm_t[8][32];
    __shared__ float  sm_wT[8][4][33];
    __shared__ float2 sm_h[8][32];      // normalized head (64 floats / warp)

    const int warp = threadIdx.x >> 5;
    const int lane = threadIdx.x & 31;
    const int w = blockIdx.x * 8 + warp;
    const int f = lane >> 3;

    const float*  ego    = sel_in ? g_buf1 : g_buf0;
    float*        fe     = sel_in ? g_buf0 : g_buf1;   // only written in mode 1 (sel_in=0)
    const float4* dinvC  = reinterpret_cast<const float4*>(dsel ? g_dinvB : g_dinvA);
    float4*       dinvN  = reinterpret_cast<float4*>(dsel ? g_dinvA : g_dinvB);
    const float4* normA  = reinterpret_cast<const float4*>(g_normA);

    const int s = g_ptr[w], e = g_ptr[w + 1];

    // ---- message passing ----
    float2 acc = make_float2(0.f, 0.f);
    for (int base = s; base < e; base += 32) {
        int j = base + lane;
        bool valid = j < e;
        int t = valid ? g_csr_t[j] : 0;
        float4 na = valid ? normA[j] : make_float4(0.f, 0.f, 0.f, 0.f);
        sm_t[warp][lane] = t;
        sm_wT[warp][0][lane] = na.x;
        sm_wT[warp][1][lane] = na.y;
        sm_wT[warp][2][lane] = na.z;
        sm_wT[warp][3][lane] = na.w;
        __syncwarp();
        int cnt = min(32, e - base);
        #pragma unroll 8
        for (int k = 0; k < cnt; k++) {
            int   tk = sm_t[warp][k];
            float wk = sm_wT[warp][f][k];
            float2 ev = __half22float2(g_egoS[tk * 32 + lane]);
            acc.x += wk * ev.x;
            acc.y += wk * ev.y;
        }
        __syncwarp();
    }
    {
        float4 dh = dinvC[w];
        float ds = (f == 0) ? dh.x : (f == 1) ? dh.y : (f == 2) ? dh.z : dh.w;
        acc.x *= ds; acc.y *= ds;
    }

    if (mode == 2) {
        // final: out = (initial_ego(buf0) + layer1_input(buf1) + fe)/3
        float2 a = reinterpret_cast<const float2*>(g_buf0 + w * kD)[lane];
        float2 b = reinterpret_cast<const float2*>(ego + w * kD)[lane];
        float2 o;
        o.x = (a.x + b.x + acc.x) * (1.0f / 3.0f);
        o.y = (a.y + b.y + acc.y) * (1.0f / 3.0f);
        reinterpret_cast<float2*>(out + w * kD)[lane] = o;
        return;
    }

    if (mode == 1)
        reinterpret_cast<float2*>(fe + w * kD)[lane] = acc;

    // ---- head inverse norm (per 8-lane group = one factor) ----
    float ss = acc.x * acc.x + acc.y * acc.y;
    #pragma unroll
    for (int o = 4; o >= 1; o >>= 1) ss += __shfl_xor_sync(0xffffffffu, ss, o);
    const float hinv = 1.0f / fmaxf(sqrtf(ss), 1e-12f);
    sm_h[warp][lane] = make_float2(acc.x * hinv, acc.y * hinv);
    __syncwarp();

    // ---- routing: half-warp per edge ----
    // lane = half*16 + r; r owns dims [4r, 4r+3]; factor fr = r>>2.
    const float4* hp4 = reinterpret_cast<const float4*>(&sm_h[warp][0]);
    const int half = lane >> 4;
    const int r    = lane & 15;
    const int fr   = r >> 2;
    const bool fl  = (r & 3) == 0;    // factor-leader lane
    float dv = 0.f;
    #pragma unroll 2
    for (int b = s; b < e; b += 2) {
        int j = b + half;
        bool valid = j < e;
        int t = valid ? g_csr_t[j] : 0;
        uint2 tv = reinterpret_cast<const uint2*>(g_TnV)[t * 16 + r];
        float4 hv = hp4[r];
        float2 t0 = __half22float2(*reinterpret_cast<__half2*>(&tv.x));
        float2 t1 = __half22float2(*reinterpret_cast<__half2*>(&tv.y));
        float p = hv.x*t0.x + hv.y*t0.y + hv.z*t1.x + hv.w*t1.y;
        p += __shfl_xor_sync(0xffffffffu, p, 1);
        p += __shfl_xor_sync(0xffffffffu, p, 2);
        // lanes r%4==0 hold q for factor fr of edge j
        float An = 0.f;
        if (fl && valid) An = g_A[j * 4 + fr] + p;
        float m = fmaxf(An, __shfl_xor_sync(0xffffffffu, An, 4));
        m = fmaxf(m, __shfl_xor_sync(0xffffffffu, m, 8));
        float ex = __expf(An - m);
        float sm = ex + __shfl_xor_sync(0xffffffffu, ex, 4);
        sm += __shfl_xor_sync(0xffffffffu, sm, 8);
        if (fl && valid) {
            float nA = ex / sm;
            g_A[j * 4 + fr]     = An;
            g_normA[j * 4 + fr] = nA;
            dv += nA;
        }
    }
    // combine halves: lanes {0,4,8,12} then hold total dval per factor
    dv += __shfl_xor_sync(0xffffffffu, dv, 16);
    float d1 = __shfl_sync(0xffffffffu, dv, 4);
    float d2 = __shfl_sync(0xffffffffu, dv, 8);
    float d3 = __shfl_sync(0xffffffffu, dv, 12);
    if (lane == 0) {
        dinvN[w] = make_float4(rsqrtf(fmaxf(dv, 1e-8f)),
                               rsqrtf(fmaxf(d1, 1e-8f)),
                               rsqrtf(fmaxf(d2, 1e-8f)),
                               rsqrtf(fmaxf(d3, 1e-8f)));
    }
}

// ---------------- host driver ----------------
extern "C" void kernel_launch(void* const* d_in, const int* in_sizes, int n_in,
                              void* d_out, int out_size) {
    const float* user = (const float*)d_in[0];
    const float* item = (const float*)d_in[1];
    const int*   hl   = (const int*)d_in[2];
    const int*   tl   = (const int*)d_in[3];
    float* out = (float*)d_out;

    const int TB = 256;
    k_init_ego<<<(kN * kD + TB - 1) / TB, TB>>>(user, item);
    k_zero_cnt<<<(kN + TB - 1) / TB, TB>>>();
    k_init_A<<<(kE + TB - 1) / TB, TB>>>();
    k_count<<<(kE + TB - 1) / TB, TB>>>(hl);
    k_chunk_reduce<<<kNChunk, TB>>>();
    k_bsum_scan<<<1, 32>>>();
    k_chunk_scan<<<kNChunk, TB>>>();
    k_fill<<<(kE + TB - 1) / TB, TB>>>(hl, tl);
    k_dinv0<<<(kN + TB - 1) / TB, TB>>>();

    const int FG = kN / 8;   // 8 warps / block
    const int RG = (kN * 4 + TB - 1) / TB;
    // layer 0: ego=buf0 -> fe=buf1
    k_tail<<<RG, TB>>>(0);                      // Tn(buf0) fp16, egoS = buf0*dinvA(init)
    k_fused<<<FG, TB>>>(0, 0, 0, out);          // it0: reads dinvA, writes dinvB; no fe
    k_rescale<<<RG, TB>>>(0);                   // egoS = buf0*dinvB
    k_fused<<<FG, TB>>>(0, 1, 1, out);          // it1: reads dinvB, writes dinvA; fe->buf1
    // layer 1: ego=buf1 -> out
    k_tail<<<RG, TB>>>(1);                      // Tn(buf1) fp16, egoS = buf1*dinvA
    k_fused<<<FG, TB>>>(1, 0, 0, out);          // it0: reads dinvA, writes dinvB; no fe
    k_rescale<<<RG, TB>>>(1);                   // egoS = buf1*dinvB
    k_fused<<<FG, TB>>>(1, 1, 2, out);          // final: reads dinvB, no routing
    (void)in_sizes; (void)n_in; (void)out_size;
}